// round 1
// baseline (speedup 1.0000x reference)
#include <cuda_runtime.h>

typedef unsigned long long u64;

__device__ __forceinline__ u64 pk2(float lo, float hi){
  u64 r; asm("mov.b64 %0, {%1, %2};" : "=l"(r) : "f"(lo), "f"(hi)); return r;
}
__device__ __forceinline__ void upk2(u64 v, float& lo, float& hi){
  asm("mov.b64 {%0, %1}, %2;" : "=f"(lo), "=f"(hi) : "l"(v));
}
__device__ __forceinline__ u64 ffma2(u64 a, u64 b, u64 c){
  u64 r; asm("fma.rn.f32x2 %0, %1, %2, %3;" : "=l"(r) : "l"(a), "l"(b), "l"(c)); return r;
}

#define NWARP 8

// Fused PillarVFE:
//  pre[n,o] = A[o]*x_n + B[o]*y_n + C[o]*z_n + D[o]*w_n + bias_p[o]
//  out[o]   = max( max_{n<npts} pre[n,o], npts<32 ? bn_bias[o] : -inf, 0 )
// where all coefficients fold the 1x1 conv (with duplicated xc/yc channels),
// the per-pillar centering constants, and the BN scale/shift.
__global__ __launch_bounds__(256) void pillar_vfe_kernel(
    const float4* __restrict__ voxels,   // [P,32] xyzw
    const float*  __restrict__ W,        // [64,9]
    const float*  __restrict__ gamma,
    const float*  __restrict__ beta,
    const float*  __restrict__ rmean,
    const float*  __restrict__ rvar,
    const int*    __restrict__ vnum,     // [P]
    const int*    __restrict__ vcoords,  // [P,4] (b,z,y,x)
    float*        __restrict__ out,      // [P,64]
    int P)
{
  __shared__ float cf[10][64];          // folded coefficients
  __shared__ float shp[NWARP][4][32];   // transposed point staging (x|y|z|w rows)

  int tid = threadIdx.x;
  if (tid < 64) {
    int o = tid;
    float s = gamma[o] / sqrtf(rvar[o] + 1e-3f);
    const float* w = W + o * 9;
    float w0=w[0], w1=w[1], w2=w[2], w3=w[3], w4=w[4], w5=w[5], w6=w[6], w7=w[7], w8=w[8];
    float S0 = w0 + w7, S1 = w1 + w8;   // xc / yc channels are duplicated (c0+c7, c1+c8)
    cf[0][o] = s * (S0 + w4);           // * x
    cf[1][o] = s * (S1 + w5);           // * y
    cf[2][o] = s * (w2 + w6);           // * z
    cf[3][o] = s * w3;                  // * intensity
    cf[4][o] = s * S0;                  // * cx
    cf[5][o] = s * S1;                  // * cy
    cf[6][o] = s * w4;                  // * mx
    cf[7][o] = s * w5;                  // * my
    cf[8][o] = s * w6;                  // * mz
    cf[9][o] = beta[o] - rmean[o] * s;  // BN bias (also the masked-point pre-activation)
  }
  __syncthreads();

  int lane = tid & 31;
  int wrp  = tid >> 5;
  int p = blockIdx.x * NWARP + wrp;
  if (p >= P) return;

  // Coalesced load: lane l owns point l of pillar p (one LDG.128 per lane).
  float4 v = voxels[(size_t)p * 32 + lane];
  int np = vnum[p];
  int2 cyx = *reinterpret_cast<const int2*>(vcoords + (size_t)p * 4 + 2); // (y, x)
  float cx = (float)cyx.y * 0.16f + 0.08f;
  float cy = (float)cyx.x * 0.16f - 39.6f;

  // Mean over ALL 32 points (reference sums unmasked), divided by npts.
  float sx = v.x, sy = v.y, sz = v.z;
  #pragma unroll
  for (int off = 16; off; off >>= 1) {
    sx += __shfl_xor_sync(0xffffffffu, sx, off);
    sy += __shfl_xor_sync(0xffffffffu, sy, off);
    sz += __shfl_xor_sync(0xffffffffu, sz, off);
  }
  float rn = 1.0f / (float)np;
  float mx = sx * rn, my = sy * rn, mz = sz * rn;

  // Transposed staging for packed point-pair loads.
  shp[wrp][0][lane] = v.x;
  shp[wrp][1][lane] = v.y;
  shp[wrp][2][lane] = v.z;
  shp[wrp][3][lane] = v.w;
  __syncwarp();

  // Each lane owns channels (lane, lane+32).
  int c0 = lane, c1 = lane + 32;
  float A0 = cf[0][c0], B0 = cf[1][c0], C0 = cf[2][c0], D0 = cf[3][c0];
  float A1 = cf[0][c1], B1 = cf[1][c1], C1 = cf[2][c1], D1 = cf[3][c1];
  float bb0 = cf[9][c0], bb1 = cf[9][c1];
  float bias0 = bb0 - cx*cf[4][c0] - cy*cf[5][c0] - mx*cf[6][c0] - my*cf[7][c0] - mz*cf[8][c0];
  float bias1 = bb1 - cx*cf[4][c1] - cy*cf[5][c1] - mx*cf[6][c1] - my*cf[7][c1] - mz*cf[8][c1];

  u64 pA0=pk2(A0,A0), pB0=pk2(B0,B0), pC0=pk2(C0,C0), pD0=pk2(D0,D0), pE0=pk2(bias0,bias0);
  u64 pA1=pk2(A1,A1), pB1=pk2(B1,B1), pC1=pk2(C1,C1), pD1=pk2(D1,D1), pE1=pk2(bias1,bias1);

  float m0 = -3.4e38f, m1 = -3.4e38f;
  const u64* sx2 = reinterpret_cast<const u64*>(&shp[wrp][0][0]);
  const u64* sy2 = reinterpret_cast<const u64*>(&shp[wrp][1][0]);
  const u64* sz2 = reinterpret_cast<const u64*>(&shp[wrp][2][0]);
  const u64* sw2 = reinterpret_cast<const u64*>(&shp[wrp][3][0]);

  int npair = np >> 1;
  for (int j = 0; j < npair; j++) {
    u64 x2 = sx2[j], y2 = sy2[j], z2 = sz2[j], w2 = sw2[j];   // LDS.64 broadcast
    u64 t0 = ffma2(pA0, x2, pE0);
    t0 = ffma2(pB0, y2, t0);
    t0 = ffma2(pC0, z2, t0);
    t0 = ffma2(pD0, w2, t0);
    u64 t1 = ffma2(pA1, x2, pE1);
    t1 = ffma2(pB1, y2, t1);
    t1 = ffma2(pC1, z2, t1);
    t1 = ffma2(pD1, w2, t1);
    float a, b, c, d;
    upk2(t0, a, b);
    upk2(t1, c, d);
    m0 = fmaxf(m0, fmaxf(a, b));
    m1 = fmaxf(m1, fmaxf(c, d));
  }
  if (np & 1) {   // scalar tail for odd npts
    int j = np - 1;
    float xs = shp[wrp][0][j], ys = shp[wrp][1][j], zs = shp[wrp][2][j], ws = shp[wrp][3][j];
    m0 = fmaxf(m0, fmaf(A0, xs, fmaf(B0, ys, fmaf(C0, zs, fmaf(D0, ws, bias0)))));
    m1 = fmaxf(m1, fmaf(A1, xs, fmaf(B1, ys, fmaf(C1, zs, fmaf(D1, ws, bias1)))));
  }
  // Masked (zero-feature) points contribute relu(bn_bias); include iff npts < N.
  if (np < 32) { m0 = fmaxf(m0, bb0); m1 = fmaxf(m1, bb1); }

  out[(size_t)p * 64 + lane]      = fmaxf(m0, 0.0f);
  out[(size_t)p * 64 + 32 + lane] = fmaxf(m1, 0.0f);
}

extern "C" void kernel_launch(void* const* d_in, const int* in_sizes, int n_in,
                              void* d_out, int out_size) {
  const float4* voxels = (const float4*)d_in[0];
  const float*  W      = (const float*)d_in[1];
  const float*  gamma  = (const float*)d_in[2];
  const float*  beta   = (const float*)d_in[3];
  const float*  rmean  = (const float*)d_in[4];
  const float*  rvar   = (const float*)d_in[5];
  const int*    vnum   = (const int*)d_in[6];
  const int*    vcrd   = (const int*)d_in[7];
  float* out = (float*)d_out;

  int P = in_sizes[6];                       // number of pillars
  int blocks = (P + NWARP - 1) / NWARP;
  pillar_vfe_kernel<<<blocks, 256>>>(voxels, W, gamma, beta, rmean, rvar,
                                     vnum, vcrd, out, P);
}

// round 2
// speedup vs baseline: 1.0111x; 1.0111x over previous
#include <cuda_runtime.h>

typedef unsigned long long u64;

__device__ __forceinline__ u64 pk2(float lo, float hi){
  u64 r; asm("mov.b64 %0, {%1, %2};" : "=l"(r) : "f"(lo), "f"(hi)); return r;
}
__device__ __forceinline__ void upk2(u64 v, float& lo, float& hi){
  asm("mov.b64 {%0, %1}, %2;" : "=f"(lo), "=f"(hi) : "l"(v));
}
__device__ __forceinline__ u64 ffma2(u64 a, u64 b, u64 c){
  u64 r; asm("fma.rn.f32x2 %0, %1, %2, %3;" : "=l"(r) : "l"(a), "l"(b), "l"(c)); return r;
}
__device__ __forceinline__ u64 fmul2(u64 a, u64 b){
  u64 r; asm("mul.rn.f32x2 %0, %1, %2;" : "=l"(r) : "l"(a), "l"(b)); return r;
}

#define NWARP 8

// Fused PillarVFE. Per point n:  pre[n,o] = A[o]x + B[o]y + C[o]z + D[o]w + bias_p[o]
// out[o] = max( max_{n<npts} pre, npts<32 ? bn_bias[o] : -inf, 0 )
// bias_p is constant over n, so we compute max over UNBIASED dots in the loop
// and add bias once at the end (exact under max-monotonicity).
__global__ __launch_bounds__(256, 6) void pillar_vfe_kernel(
    const float4* __restrict__ voxels,   // [P,32] xyzw
    const float*  __restrict__ W,        // [64,9]
    const float*  __restrict__ gamma,
    const float*  __restrict__ beta,
    const float*  __restrict__ rmean,
    const float*  __restrict__ rvar,
    const int*    __restrict__ vnum,     // [P]
    const int*    __restrict__ vcoords,  // [P,4] (b,z,y,x)
    float*        __restrict__ out,      // [P,64]
    int P)
{
  __shared__ float cf[10][64];          // folded coefficients
  __shared__ float shp[NWARP][4][32];   // transposed point staging (x|y|z|w rows)

  int tid = threadIdx.x;
  if (tid < 64) {
    int o = tid;
    float s = gamma[o] / sqrtf(rvar[o] + 1e-3f);
    const float* w = W + o * 9;
    float w0=w[0], w1=w[1], w2=w[2], w3=w[3], w4=w[4], w5=w[5], w6=w[6], w7=w[7], w8=w[8];
    float S0 = w0 + w7, S1 = w1 + w8;   // xc / yc channels are duplicated (c0+c7, c1+c8)
    cf[0][o] = s * (S0 + w4);           // * x
    cf[1][o] = s * (S1 + w5);           // * y
    cf[2][o] = s * (w2 + w6);           // * z
    cf[3][o] = s * w3;                  // * intensity
    cf[4][o] = s * S0;                  // * cx
    cf[5][o] = s * S1;                  // * cy
    cf[6][o] = s * w4;                  // * mx
    cf[7][o] = s * w5;                  // * my
    cf[8][o] = s * w6;                  // * mz
    cf[9][o] = beta[o] - rmean[o] * s;  // BN bias (= masked-point pre-activation)
  }

  int lane = tid & 31;
  int wrp  = tid >> 5;
  int p = blockIdx.x * NWARP + wrp;

  // Issue the global loads before the barrier so they overlap it.
  float4 v = make_float4(0.f, 0.f, 0.f, 0.f);
  int np = 1;
  int2 cyx = make_int2(0, 0);
  if (p < P) {
    v   = voxels[(size_t)p * 32 + lane];                              // LDG.128 coalesced
    np  = vnum[p];
    cyx = *reinterpret_cast<const int2*>(vcoords + (size_t)p * 4 + 2); // (y, x)
  }
  __syncthreads();
  if (p >= P) return;

  // Mean over ALL 32 points (reference sums unmasked), divided by npts.
  float sx = v.x, sy = v.y, sz = v.z;
  #pragma unroll
  for (int off = 16; off; off >>= 1) {
    sx += __shfl_xor_sync(0xffffffffu, sx, off);
    sy += __shfl_xor_sync(0xffffffffu, sy, off);
    sz += __shfl_xor_sync(0xffffffffu, sz, off);
  }
  float rn = 1.0f / (float)np;
  float mx = sx * rn, my = sy * rn, mz = sz * rn;

  // Transposed staging for packed point loads.
  shp[wrp][0][lane] = v.x;
  shp[wrp][1][lane] = v.y;
  shp[wrp][2][lane] = v.z;
  shp[wrp][3][lane] = v.w;
  __syncwarp();

  // Each lane owns channels (lane, lane+32): conflict-free cf reads.
  int c0 = lane, c1 = lane + 32;
  float A0 = cf[0][c0], B0 = cf[1][c0], C0 = cf[2][c0], D0 = cf[3][c0];
  float A1 = cf[0][c1], B1 = cf[1][c1], C1 = cf[2][c1], D1 = cf[3][c1];
  float bb0 = cf[9][c0], bb1 = cf[9][c1];

  // Per-pillar bias (computed pre-loop; latency hidden by other warps).
  float cx = fmaf((float)cyx.y, 0.16f, 0.08f);
  float cy = fmaf((float)cyx.x, 0.16f, -39.6f);
  float bias0 = bb0 - cx*cf[4][c0] - cy*cf[5][c0] - mx*cf[6][c0] - my*cf[7][c0] - mz*cf[8][c0];
  float bias1 = bb1 - cx*cf[4][c1] - cy*cf[5][c1] - mx*cf[6][c1] - my*cf[7][c1] - mz*cf[8][c1];

  // Duplicated packed coefficients for point-pair FFMA2.
  u64 pA0=pk2(A0,A0), pB0=pk2(B0,B0), pC0=pk2(C0,C0), pD0=pk2(D0,D0);
  u64 pA1=pk2(A1,A1), pB1=pk2(B1,B1), pC1=pk2(C1,C1), pD1=pk2(D1,D1);

  const ulonglong2* rx = reinterpret_cast<const ulonglong2*>(&shp[wrp][0][0]);
  const ulonglong2* ry = reinterpret_cast<const ulonglong2*>(&shp[wrp][1][0]);
  const ulonglong2* rz = reinterpret_cast<const ulonglong2*>(&shp[wrp][2][0]);
  const ulonglong2* rw = reinterpret_cast<const ulonglong2*>(&shp[wrp][3][0]);

  float m0 = -3.4e38f, m1 = -3.4e38f;
  int nq = np >> 2;                     // full quads of 4 points
  #pragma unroll 2
  for (int q = 0; q < nq; q++) {
    ulonglong2 X = rx[q], Y = ry[q];    // LDS.128 broadcast, pts (4q..4q+3)
    ulonglong2 Z = rz[q], Wv = rw[q];

    u64 s01 = fmul2(pA0, X.x);  s01 = ffma2(pB0, Y.x, s01);
    u64 s23 = fmul2(pA0, X.y);  s23 = ffma2(pB0, Y.y, s23);
    u64 r01 = fmul2(pA1, X.x);  r01 = ffma2(pB1, Y.x, r01);
    u64 r23 = fmul2(pA1, X.y);  r23 = ffma2(pB1, Y.y, r23);
    s01 = ffma2(pC0, Z.x, s01); s01 = ffma2(pD0, Wv.x, s01);
    s23 = ffma2(pC0, Z.y, s23); s23 = ffma2(pD0, Wv.y, s23);
    r01 = ffma2(pC1, Z.x, r01); r01 = ffma2(pD1, Wv.x, r01);
    r23 = ffma2(pC1, Z.y, r23); r23 = ffma2(pD1, Wv.y, r23);

    float a,b,c,d;
    upk2(s01, a, b); upk2(s23, c, d);
    m0 = fmaxf(m0, fmaxf(fmaxf(a, b), fmaxf(c, d)));
    upk2(r01, a, b); upk2(r23, c, d);
    m1 = fmaxf(m1, fmaxf(fmaxf(a, b), fmaxf(c, d)));
  }
  // Scalar tail (np % 4 points).
  for (int r = nq << 2; r < np; r++) {
    float xs = shp[wrp][0][r], ys = shp[wrp][1][r];
    float zs = shp[wrp][2][r], ws = shp[wrp][3][r];
    m0 = fmaxf(m0, fmaf(A0, xs, fmaf(B0, ys, fmaf(C0, zs, D0 * ws))));
    m1 = fmaxf(m1, fmaf(A1, xs, fmaf(B1, ys, fmaf(C1, zs, D1 * ws))));
  }

  float f0 = fmaxf(m0 + bias0, 0.0f);
  float f1 = fmaxf(m1 + bias1, 0.0f);
  if (np < 32) {                        // masked points contribute relu(bn_bias)
    f0 = fmaxf(f0, bb0);
    f1 = fmaxf(f1, bb1);
  }
  out[(size_t)p * 64 + lane]      = f0;
  out[(size_t)p * 64 + 32 + lane] = f1;
}

extern "C" void kernel_launch(void* const* d_in, const int* in_sizes, int n_in,
                              void* d_out, int out_size) {
  const float4* voxels = (const float4*)d_in[0];
  const float*  W      = (const float*)d_in[1];
  const float*  gamma  = (const float*)d_in[2];
  const float*  beta   = (const float*)d_in[3];
  const float*  rmean  = (const float*)d_in[4];
  const float*  rvar   = (const float*)d_in[5];
  const int*    vnum   = (const int*)d_in[6];
  const int*    vcrd   = (const int*)d_in[7];
  float* out = (float*)d_out;

  int P = in_sizes[6];
  int blocks = (P + NWARP - 1) / NWARP;
  pillar_vfe_kernel<<<blocks, 256>>>(voxels, W, gamma, beta, rmean, rvar,
                                     vnum, vcrd, out, P);
}

// round 3
// speedup vs baseline: 1.0430x; 1.0315x over previous
#include <cuda_runtime.h>

typedef unsigned long long u64;

__device__ __forceinline__ u64 pk2(float lo, float hi){
  u64 r; asm("mov.b64 %0, {%1, %2};" : "=l"(r) : "f"(lo), "f"(hi)); return r;
}
__device__ __forceinline__ void upk2(u64 v, float& lo, float& hi){
  asm("mov.b64 {%0, %1}, %2;" : "=f"(lo), "=f"(hi) : "l"(v));
}
__device__ __forceinline__ u64 ffma2(u64 a, u64 b, u64 c){
  u64 r; asm("fma.rn.f32x2 %0, %1, %2, %3;" : "=l"(r) : "l"(a), "l"(b), "l"(c)); return r;
}
__device__ __forceinline__ u64 fmul2(u64 a, u64 b){
  u64 r; asm("mul.rn.f32x2 %0, %1, %2;" : "=l"(r) : "l"(a), "l"(b)); return r;
}

#define NWARP 8
#define GRID_BLOCKS 912   // 152 SMs * 6 resident blocks

// Fused PillarVFE, persistent warps. Per point n:
//   pre[n,o] = A[o]x + B[o]y + C[o]z + D[o]w + bias_p[o]
//   out[o] = max( max_{n<npts} pre, npts<32 ? bn_bias[o] : -inf, 0 )
// Loop computes max over UNBIASED dots; bias added once (max-monotone).
// Lanes >= npts stage point 0's coords (max is idempotent) so the quad loop
// has no scalar tail.
__global__ __launch_bounds__(256, 5) void pillar_vfe_kernel(
    const float4* __restrict__ voxels,   // [P,32] xyzw
    const float*  __restrict__ W,        // [64,9]
    const float*  __restrict__ gamma,
    const float*  __restrict__ beta,
    const float*  __restrict__ rmean,
    const float*  __restrict__ rvar,
    const int*    __restrict__ vnum,     // [P]
    const int*    __restrict__ vcoords,  // [P,4] (b,z,y,x)
    float*        __restrict__ out,      // [P,64]
    int P)
{
  __shared__ float cf[10][64];          // folded coefficients
  __shared__ float shp[NWARP][4][32];   // transposed point staging (x|y|z|w rows)

  int tid = threadIdx.x;
  if (tid < 64) {
    int o = tid;
    float s = gamma[o] / sqrtf(rvar[o] + 1e-3f);
    const float* w = W + o * 9;
    float w0=w[0], w1=w[1], w2=w[2], w3=w[3], w4=w[4], w5=w[5], w6=w[6], w7=w[7], w8=w[8];
    float S0 = w0 + w7, S1 = w1 + w8;   // xc / yc channels duplicated (c0+c7, c1+c8)
    cf[0][o] = s * (S0 + w4);           // * x
    cf[1][o] = s * (S1 + w5);           // * y
    cf[2][o] = s * (w2 + w6);           // * z
    cf[3][o] = s * w3;                  // * intensity
    cf[4][o] = s * S0;                  // * cx
    cf[5][o] = s * S1;                  // * cy
    cf[6][o] = s * w4;                  // * mx
    cf[7][o] = s * w5;                  // * my
    cf[8][o] = s * w6;                  // * mz
    cf[9][o] = beta[o] - rmean[o] * s;  // BN bias (= masked-point pre-activation)
  }
  __syncthreads();

  int lane = tid & 31;
  int wrp  = tid >> 5;
  int NW   = gridDim.x * NWARP;         // total warps = pillar stride
  int p    = blockIdx.x * NWARP + wrp;
  if (p >= P) return;

  // Hoisted per-warp channel constants (channels lane, lane+32).
  int c0 = lane, c1 = lane + 32;
  u64 pA0 = pk2(cf[0][c0], cf[0][c0]), pB0 = pk2(cf[1][c0], cf[1][c0]);
  u64 pC0 = pk2(cf[2][c0], cf[2][c0]), pD0 = pk2(cf[3][c0], cf[3][c0]);
  u64 pA1 = pk2(cf[0][c1], cf[0][c1]), pB1 = pk2(cf[1][c1], cf[1][c1]);
  u64 pC1 = pk2(cf[2][c1], cf[2][c1]), pD1 = pk2(cf[3][c1], cf[3][c1]);
  float bb0 = cf[9][c0], bb1 = cf[9][c1];

  const ulonglong2* rx = reinterpret_cast<const ulonglong2*>(&shp[wrp][0][0]);
  const ulonglong2* ry = reinterpret_cast<const ulonglong2*>(&shp[wrp][1][0]);
  const ulonglong2* rz = reinterpret_cast<const ulonglong2*>(&shp[wrp][2][0]);
  const ulonglong2* rw = reinterpret_cast<const ulonglong2*>(&shp[wrp][3][0]);

  // Current pillar state.
  float4 v  = voxels[(size_t)p * 32 + lane];                              // LDG.128
  int np    = vnum[p];
  int2 cyx  = *reinterpret_cast<const int2*>(vcoords + (size_t)p * 4 + 2); // (y,x)

  for (;;) {
    // ---- Prefetch next pillar (hides DRAM latency behind this pillar's compute).
    int pn = p + NW;
    bool more = (pn < P);
    float4 vN; int npN = 0; int2 cyxN = make_int2(0, 0);
    if (more) {
      vN   = voxels[(size_t)pn * 32 + lane];
      npN  = vnum[pn];
      cyxN = *reinterpret_cast<const int2*>(vcoords + (size_t)pn * 4 + 2);
    }

    // ---- Mean over ALL 32 points (reference sums unmasked), / npts.
    float sx = v.x, sy = v.y, sz = v.z;
    #pragma unroll
    for (int off = 16; off; off >>= 1) {
      sx += __shfl_xor_sync(0xffffffffu, sx, off);
      sy += __shfl_xor_sync(0xffffffffu, sy, off);
      sz += __shfl_xor_sync(0xffffffffu, sz, off);
    }
    float rn = 1.0f / (float)np;
    float mx = sx * rn, my = sy * rn, mz = sz * rn;

    // ---- Stage transposed points; pad invalid lanes with point 0 (max-idempotent).
    float x0 = __shfl_sync(0xffffffffu, v.x, 0);
    float y0 = __shfl_sync(0xffffffffu, v.y, 0);
    float z0 = __shfl_sync(0xffffffffu, v.z, 0);
    float w0 = __shfl_sync(0xffffffffu, v.w, 0);
    bool valid = (lane < np);
    __syncwarp();                        // prior iter's LDS reads done before overwrite
    shp[wrp][0][lane] = valid ? v.x : x0;
    shp[wrp][1][lane] = valid ? v.y : y0;
    shp[wrp][2][lane] = valid ? v.z : z0;
    shp[wrp][3][lane] = valid ? v.w : w0;
    __syncwarp();

    // ---- Quad loop: fully unrolled, guarded; immediate LDS offsets.
    float m0 = -3.4e38f, m1 = -3.4e38f;
    int trips = (np + 3) >> 2;           // 1..8
    #pragma unroll
    for (int q = 0; q < 8; q++) {
      if (q >= trips) break;
      ulonglong2 X = rx[q], Y = ry[q];   // LDS.128 broadcast, pts 4q..4q+3
      ulonglong2 Z = rz[q], Wv = rw[q];

      u64 s01 = fmul2(pA0, X.x);  s01 = ffma2(pB0, Y.x, s01);
      u64 s23 = fmul2(pA0, X.y);  s23 = ffma2(pB0, Y.y, s23);
      u64 r01 = fmul2(pA1, X.x);  r01 = ffma2(pB1, Y.x, r01);
      u64 r23 = fmul2(pA1, X.y);  r23 = ffma2(pB1, Y.y, r23);
      s01 = ffma2(pC0, Z.x, s01); s01 = ffma2(pD0, Wv.x, s01);
      s23 = ffma2(pC0, Z.y, s23); s23 = ffma2(pD0, Wv.y, s23);
      r01 = ffma2(pC1, Z.x, r01); r01 = ffma2(pD1, Wv.x, r01);
      r23 = ffma2(pC1, Z.y, r23); r23 = ffma2(pD1, Wv.y, r23);

      float a, b, c, d;
      upk2(s01, a, b); upk2(s23, c, d);
      m0 = fmaxf(m0, fmaxf(fmaxf(a, b), fmaxf(c, d)));
      upk2(r01, a, b); upk2(r23, c, d);
      m1 = fmaxf(m1, fmaxf(fmaxf(a, b), fmaxf(c, d)));
    }

    // ---- Per-pillar bias (off the loop's critical path), ReLU, store.
    float cx = fmaf((float)cyx.y, 0.16f, 0.08f);
    float cy = fmaf((float)cyx.x, 0.16f, -39.6f);
    float bias0 = bb0 - cx*cf[4][c0] - cy*cf[5][c0] - mx*cf[6][c0] - my*cf[7][c0] - mz*cf[8][c0];
    float bias1 = bb1 - cx*cf[4][c1] - cy*cf[5][c1] - mx*cf[6][c1] - my*cf[7][c1] - mz*cf[8][c1];
    float f0 = fmaxf(m0 + bias0, 0.0f);
    float f1 = fmaxf(m1 + bias1, 0.0f);
    if (np < 32) {                       // masked points contribute relu(bn_bias)
      f0 = fmaxf(f0, bb0);
      f1 = fmaxf(f1, bb1);
    }
    out[(size_t)p * 64 + lane]      = f0;
    out[(size_t)p * 64 + 32 + lane] = f1;

    if (!more) break;
    v = vN; np = npN; cyx = cyxN; p = pn;
  }
}

extern "C" void kernel_launch(void* const* d_in, const int* in_sizes, int n_in,
                              void* d_out, int out_size) {
  const float4* voxels = (const float4*)d_in[0];
  const float*  W      = (const float*)d_in[1];
  const float*  gamma  = (const float*)d_in[2];
  const float*  beta   = (const float*)d_in[3];
  const float*  rmean  = (const float*)d_in[4];
  const float*  rvar   = (const float*)d_in[5];
  const int*    vnum   = (const int*)d_in[6];
  const int*    vcrd   = (const int*)d_in[7];
  float* out = (float*)d_out;

  int P = in_sizes[6];
  int needed = (P + NWARP - 1) / NWARP;
  int blocks = needed < GRID_BLOCKS ? needed : GRID_BLOCKS;
  pillar_vfe_kernel<<<blocks, 256>>>(voxels, W, gamma, beta, rmean, rvar,
                                     vnum, vcrd, out, P);
}

// round 5
// speedup vs baseline: 1.1098x; 1.0640x over previous
#include <cuda_runtime.h>

typedef unsigned long long u64;

__device__ __forceinline__ u64 pk2(float lo, float hi){
  u64 r; asm("mov.b64 %0, {%1, %2};" : "=l"(r) : "f"(lo), "f"(hi)); return r;
}
__device__ __forceinline__ void upk2(u64 v, float& lo, float& hi){
  asm("mov.b64 {%0, %1}, %2;" : "=f"(lo), "=f"(hi) : "l"(v));
}
__device__ __forceinline__ u64 ffma2(u64 a, u64 b, u64 c){
  u64 r; asm("fma.rn.f32x2 %0, %1, %2, %3;" : "=l"(r) : "l"(a), "l"(b), "l"(c)); return r;
}
__device__ __forceinline__ u64 fmul2(u64 a, u64 b){
  u64 r; asm("mul.rn.f32x2 %0, %1, %2;" : "=l"(r) : "l"(a), "l"(b)); return r;
}
__device__ __forceinline__ u64 fadd2(u64 a, u64 b){
  u64 r; asm("add.rn.f32x2 %0, %1, %2;" : "=l"(r) : "l"(a), "l"(b)); return r;
}

#define NWARP 8
#define GRID_BLOCKS 608   // 152 SMs * 4 resident blocks

// Fused PillarVFE, persistent warps.
//   pre[n,o] = A[o]x + B[o]y + C[o]z + D[o]w + bias_p[o]
//   out[o]   = max( max_{n<npts} pre, npts<32 ? bn_bias[o] : -inf, 0 )
// Loop computes max over UNBIASED dots; per-pillar bias added once (max-monotone).
// Lanes >= npts stage point 0 (max-idempotent) -> no scalar tail.
// Lane owns channels (2*lane, 2*lane+1) -> single st.global.v2 per pillar.
__global__ __launch_bounds__(256, 4) void pillar_vfe_kernel(
    const float4* __restrict__ voxels,   // [P,32] xyzw
    const float*  __restrict__ W,        // [64,9]
    const float*  __restrict__ gamma,
    const float*  __restrict__ beta,
    const float*  __restrict__ rmean,
    const float*  __restrict__ rvar,
    const int*    __restrict__ vnum,     // [P]
    const int*    __restrict__ vcoords,  // [P,4] (b,z,y,x)
    float*        __restrict__ out,      // [P,64]
    int P)
{
  __shared__ __align__(16) float cf[10][64];           // folded coefficients
  __shared__ __align__(16) float shp[NWARP][2][4][32]; // double-buffered staging

  int tid = threadIdx.x;
  if (tid < 64) {
    int o = tid;
    float s = gamma[o] / sqrtf(rvar[o] + 1e-3f);
    const float* w = W + o * 9;
    float w0=w[0], w1=w[1], w2=w[2], w3=w[3], w4=w[4], w5=w[5], w6=w[6], w7=w[7], w8=w[8];
    float S0 = w0 + w7, S1 = w1 + w8;   // xc / yc channels duplicated (c0+c7, c1+c8)
    cf[0][o] = s * (S0 + w4);           // * x
    cf[1][o] = s * (S1 + w5);           // * y
    cf[2][o] = s * (w2 + w6);           // * z
    cf[3][o] = s * w3;                  // * intensity
    cf[4][o] = s * S0;                  // * cx
    cf[5][o] = s * S1;                  // * cy
    cf[6][o] = s * w4;                  // * mx
    cf[7][o] = s * w5;                  // * my
    cf[8][o] = s * w6;                  // * mz
    cf[9][o] = beta[o] - rmean[o] * s;  // BN bias (= masked-point pre-activation)
  }
  __syncthreads();

  int lane = tid & 31;
  int wrp  = tid >> 5;
  int NW   = gridDim.x * NWARP;
  int p    = blockIdx.x * NWARP + wrp;
  if (p >= P) return;

  // ---- Hoisted per-warp constants. Lane owns channels c0=2*lane, c1=2*lane+1.
  int c0 = 2 * lane, c1 = 2 * lane + 1;
  // Point-pair packed loop coefficients (duplicated per channel).
  u64 pA0 = pk2(cf[0][c0], cf[0][c0]), pA1 = pk2(cf[0][c1], cf[0][c1]);
  u64 pB0 = pk2(cf[1][c0], cf[1][c0]), pB1 = pk2(cf[1][c1], cf[1][c1]);
  u64 pC0 = pk2(cf[2][c0], cf[2][c0]), pC1 = pk2(cf[2][c1], cf[2][c1]);
  u64 pD0 = pk2(cf[3][c0], cf[3][c0]), pD1 = pk2(cf[3][c1], cf[3][c1]);
  // Channel-pair packed bias coefficients (negated: bias = bb - sum(...)).
  u64 ncf4 = pk2(-cf[4][c0], -cf[4][c1]);
  u64 ncf5 = pk2(-cf[5][c0], -cf[5][c1]);
  u64 ncf6 = pk2(-cf[6][c0], -cf[6][c1]);
  u64 ncf7 = pk2(-cf[7][c0], -cf[7][c1]);
  u64 ncf8 = pk2(-cf[8][c0], -cf[8][c1]);
  float bb0 = cf[9][c0], bb1 = cf[9][c1];
  u64  bb2  = pk2(bb0, bb1);
  float rbb0 = fmaxf(bb0, 0.0f), rbb1 = fmaxf(bb1, 0.0f);  // relu(bn_bias)

  float* sb0 = &shp[wrp][0][0][0];
  float* sb1 = &shp[wrp][1][0][0];
  int buf = 0;

  // ---- Current pillar state.
  float4 v  = voxels[(size_t)p * 32 + lane];                               // LDG.128
  int np    = vnum[p];
  int2 cyx  = *reinterpret_cast<const int2*>(vcoords + (size_t)p * 4 + 2); // (y,x)

  for (;;) {
    // Prefetch next pillar (hides DRAM latency behind this pillar's compute).
    int pn = p + NW;
    bool more = (pn < P);
    float4 vN; int npN = 0; int2 cyxN = make_int2(0, 0);
    if (more) {
      vN   = voxels[(size_t)pn * 32 + lane];
      npN  = vnum[pn];
      cyxN = *reinterpret_cast<const int2*>(vcoords + (size_t)pn * 4 + 2);
    }

    // Mean over ALL 32 points (reference sums unmasked), / npts.
    // Packed (x,y) butterfly: 2 SHFL + 1 fadd2 per level; z scalar.
    u64  sxy = pk2(v.x, v.y);
    float sz = v.z;
    #pragma unroll
    for (int off = 16; off; off >>= 1) {
      float lo, hi;
      upk2(sxy, lo, hi);
      float lo2 = __shfl_xor_sync(0xffffffffu, lo, off);
      float hi2 = __shfl_xor_sync(0xffffffffu, hi, off);
      sxy = fadd2(sxy, pk2(lo2, hi2));
      sz += __shfl_xor_sync(0xffffffffu, sz, off);
    }
    float rn = __fdividef(1.0f, (float)np);
    float sx, sy;
    upk2(sxy, sx, sy);
    float mx = sx * rn, my = sy * rn, mz = sz * rn;

    // Stage transposed points; pad invalid lanes with point 0 (max-idempotent).
    float x0 = __shfl_sync(0xffffffffu, v.x, 0);
    float y0 = __shfl_sync(0xffffffffu, v.y, 0);
    float z0 = __shfl_sync(0xffffffffu, v.z, 0);
    float w0 = __shfl_sync(0xffffffffu, v.w, 0);
    bool valid = (lane < np);
    float* sb = buf ? sb1 : sb0;
    sb[lane]      = valid ? v.x : x0;
    sb[32 + lane] = valid ? v.y : y0;
    sb[64 + lane] = valid ? v.z : z0;
    sb[96 + lane] = valid ? v.w : w0;
    __syncwarp();

    // Quad loop: 4 points / trip, fully unrolled with immediate LDS offsets.
    const ulonglong2* rq = reinterpret_cast<const ulonglong2*>(sb);
    float m0 = -3.4e38f, m1 = -3.4e38f;
    int trips = (np + 3) >> 2;            // 1..8
    #pragma unroll
    for (int q = 0; q < 8; q++) {
      if (q >= trips) break;
      ulonglong2 X = rq[q],      Y  = rq[8 + q];   // LDS.128 broadcast
      ulonglong2 Z = rq[16 + q], Wv = rq[24 + q];

      u64 s01 = fmul2(pA0, X.x);  s01 = ffma2(pB0, Y.x, s01);
      u64 s23 = fmul2(pA0, X.y);  s23 = ffma2(pB0, Y.y, s23);
      u64 r01 = fmul2(pA1, X.x);  r01 = ffma2(pB1, Y.x, r01);
      u64 r23 = fmul2(pA1, X.y);  r23 = ffma2(pB1, Y.y, r23);
      s01 = ffma2(pC0, Z.x, s01); s01 = ffma2(pD0, Wv.x, s01);
      s23 = ffma2(pC0, Z.y, s23); s23 = ffma2(pD0, Wv.y, s23);
      r01 = ffma2(pC1, Z.x, r01); r01 = ffma2(pD1, Wv.x, r01);
      r23 = ffma2(pC1, Z.y, r23); r23 = ffma2(pD1, Wv.y, r23);

      float a, b, c, d;
      upk2(s01, a, b); upk2(s23, c, d);   // reg-pair aliases: ~free in SASS
      m0 = fmaxf(m0, fmaxf(fmaxf(a, b), fmaxf(c, d)));
      upk2(r01, a, b); upk2(r23, c, d);
      m1 = fmaxf(m1, fmaxf(fmaxf(a, b), fmaxf(c, d)));
    }

    // Packed per-pillar bias: bias2 = bb2 - cx*cf4 - cy*cf5 - mx*cf6 - my*cf7 - mz*cf8
    float cx = fmaf((float)cyx.y, 0.16f, 0.08f);
    float cy = fmaf((float)cyx.x, 0.16f, -39.6f);
    u64 bias2 = ffma2(pk2(cx, cx), ncf4, bb2);
    bias2 = ffma2(pk2(cy, cy), ncf5, bias2);
    bias2 = ffma2(pk2(mx, mx), ncf6, bias2);
    bias2 = ffma2(pk2(my, my), ncf7, bias2);
    bias2 = ffma2(pk2(mz, mz), ncf8, bias2);

    // Epilogue: add bias, fold relu + masked-point bn contribution, store.
    u64 t2 = fadd2(pk2(m0, m1), bias2);
    float t0, t1;
    upk2(t2, t0, t1);
    float g0 = (np < 32) ? rbb0 : 0.0f;   // relu floor incl. masked points
    float g1 = (np < 32) ? rbb1 : 0.0f;
    float2 res = make_float2(fmaxf(t0, g0), fmaxf(t1, g1));
    reinterpret_cast<float2*>(out)[(size_t)p * 32 + lane] = res;  // ch (2l, 2l+1)

    if (!more) break;
    v = vN; np = npN; cyx = cyxN; p = pn; buf ^= 1;
  }
}

extern "C" void kernel_launch(void* const* d_in, const int* in_sizes, int n_in,
                              void* d_out, int out_size) {
  const float4* voxels = (const float4*)d_in[0];
  const float*  W      = (const float*)d_in[1];
  const float*  gamma  = (const float*)d_in[2];
  const float*  beta   = (const float*)d_in[3];
  const float*  rmean  = (const float*)d_in[4];
  const float*  rvar   = (const float*)d_in[5];
  const int*    vnum   = (const int*)d_in[6];
  const int*    vcrd   = (const int*)d_in[7];
  float* out = (float*)d_out;

  int P = in_sizes[6];
  int needed = (P + NWARP - 1) / NWARP;
  int blocks = needed < GRID_BLOCKS ? needed : GRID_BLOCKS;
  pillar_vfe_kernel<<<blocks, 256>>>(voxels, W, gamma, beta, rmean, rvar,
                                     vnum, vcrd, out, P);
}